// round 9
// baseline (speedup 1.0000x reference)
#include <cuda_runtime.h>
#include <cuda_bf16.h>
#include <math.h>
#include <cstdint>

#define CT 2048
#define CD 2048
#define CH 32
#define CHK 8
#define CDH 64
#define CINTER 8192

typedef __nv_bfloat16 bf16;
typedef __nv_bfloat162 bf162;

// ---------------------------------------------------------------------------
// Static device scratch
// ---------------------------------------------------------------------------
struct alignas(256) Scratch {
  float Pqkv[CT * 1536];
  float h[CT * CD];
  float skpart[4 * CT * 512];
  float ropeC[CT * 32];
  float ropeS[CT * 32];
  bf16 x[CT * CD];
  bf16 q[CH * CT * CDH];
  bf16 k[CHK * CT * CDH];
  bf16 v[CHK * CT * CDH];
  bf16 attn[CT * CD];
  bf16 Po[CT * 512];
  bf16 Pg[CT * 512];
  bf16 Pu[CT * 512];
  bf16 gate[CT * CINTER];
  bf16 up[CT * CINTER];
  bf16 Pd[CT * 512];
  bf16 qV[1024 * CD];
  bf16 kV[256 * CD];
  bf16 vV[256 * CD];
  bf16 oUs[CD * 512];
  bf16 oV[512 * CD];
  bf16 gUs[CINTER * 512];
  bf16 gV[512 * CD];
  bf16 uUs[CINTER * 512];
  bf16 uV[512 * CD];
  bf16 dUs[CD * 512];
  bf16 dV[512 * CINTER];
};
__device__ Scratch g_scratch;

// ---------------------------------------------------------------------------
// helpers
// ---------------------------------------------------------------------------
__device__ __forceinline__ void cp16(void* s, const void* g) {
  uint32_t sa = (uint32_t)__cvta_generic_to_shared(s);
  asm volatile("cp.async.cg.shared.global [%0], [%1], 16;" ::"r"(sa), "l"(g));
}
__device__ __forceinline__ void mma_bf16(float* c, const uint32_t* a,
                                         const uint32_t* b) {
  asm volatile(
      "mma.sync.aligned.m16n8k16.row.col.f32.bf16.bf16.f32 "
      "{%0,%1,%2,%3}, {%4,%5,%6,%7}, {%8,%9}, {%0,%1,%2,%3};"
      : "+f"(c[0]), "+f"(c[1]), "+f"(c[2]), "+f"(c[3])
      : "r"(a[0]), "r"(a[1]), "r"(a[2]), "r"(a[3]), "r"(b[0]), "r"(b[1]));
}
__device__ __forceinline__ void ldm4(uint32_t* r, const void* p) {
  uint32_t a = (uint32_t)__cvta_generic_to_shared(p);
  asm volatile(
      "ldmatrix.sync.aligned.m8n8.x4.shared.b16 {%0,%1,%2,%3}, [%4];"
      : "=r"(r[0]), "=r"(r[1]), "=r"(r[2]), "=r"(r[3])
      : "r"(a));
}
__device__ __forceinline__ uint32_t packbf(float a, float b) {
  bf162 v = __floats2bfloat162_rn(a, b);
  return *(uint32_t*)&v;
}

// ---------------------------------------------------------------------------
// weight conversion fp32 -> bf16
// ---------------------------------------------------------------------------
#define NCVT 11
struct CvtPack {
  const float* src[NCVT];
  bf16* dst[NCVT];
  int n4[NCVT];
};
__global__ void cvt_f2bf(CvtPack p, int total4) {
  int i = blockIdx.x * 256 + threadIdx.x;
  if (i >= total4) return;
  int s = 0, off = i;
  while (off >= p.n4[s]) { off -= p.n4[s]; s++; }
  const float4 v = ((const float4*)p.src[s])[off];
  bf162* d = (bf162*)p.dst[s];
  d[off * 2] = __floats2bfloat162_rn(v.x, v.y);
  d[off * 2 + 1] = __floats2bfloat162_rn(v.z, v.w);
}

__global__ void rope_tab(float* __restrict__ c, float* __restrict__ s) {
  const int i = blockIdx.x * 256 + threadIdx.x;
  const int t = i >> 5, d = i & 31;
  const float invf = exp2f(-0.41524101186092028f * (float)d);
  float sn, cs;
  sincosf((float)t * invf, &sn, &cs);
  c[i] = cs;
  s[i] = sn;
}

// ---------------------------------------------------------------------------
// RMSNorm (fp32 in, bf16 out)
// ---------------------------------------------------------------------------
__global__ void rmsnorm_bf(const float* __restrict__ in,
                           const float* __restrict__ w,
                           bf16* __restrict__ out) {
  const int t = blockIdx.x;
  const float* row = in + (size_t)t * CD;
  float ss = 0.f;
  for (int i = threadIdx.x; i < CD; i += 256) {
    float v = row[i];
    ss += v * v;
  }
  __shared__ float red[8];
#pragma unroll
  for (int o = 16; o > 0; o >>= 1) ss += __shfl_xor_sync(0xffffffffu, ss, o);
  if ((threadIdx.x & 31) == 0) red[threadIdx.x >> 5] = ss;
  __syncthreads();
  if (threadIdx.x == 0) {
    float v = 0.f;
#pragma unroll
    for (int i = 0; i < 8; i++) v += red[i];
    red[0] = v;
  }
  __syncthreads();
  const float inv = rsqrtf(red[0] * (1.0f / CD) + 1e-5f);
  for (int i = threadIdx.x * 2; i < CD; i += 512) {
    bf162 o = __floats2bfloat162_rn(row[i] * inv * w[i],
                                    row[i + 1] * inv * w[i + 1]);
    *(bf162*)&out[(size_t)t * CD + i] = o;
  }
}

// ---------------------------------------------------------------------------
// bf16 GEMM (NT), 4-stage cp.async pipeline. CTA tile 128 x (4*WN), KT=32.
// WN=16 -> 128x64 tile, ~85 regs, 3 CTAs/SM. WN=32 -> 128x128, 2 CTAs/SM.
// MODE 0: fp32 out (+res). 1: bf16. 2: bf16 silu. 3: bf16 *aux.
// kc>0: split-K (chunk blockIdx.z, fp32 partial to C1 + z*CT*N); else
// blockIdx.z picks the (A1..) / (A2..) problem pair.
// ---------------------------------------------------------------------------
#define GST 4

template <int MODE, int WN>
__global__ __launch_bounds__(256, (WN == 16) ? 3 : 2) void gemm_bf(
    const bf16* __restrict__ A1, const bf16* __restrict__ B1,
    const float* __restrict__ res1, void* __restrict__ C1,
    const bf16* __restrict__ A2, const bf16* __restrict__ B2,
    const float* __restrict__ res2, void* __restrict__ C2,
    const bf16* __restrict__ aux, int N, int K, int kc) {
  constexpr int BN = WN * 4;
  constexpr int GTA = 128 * 40;
  constexpr int GTB = BN * 40;
  constexpr int NF = WN / 8;   // n-fragments per warp
  constexpr int NB = WN / 16;  // b ldmatrix per ks

  extern __shared__ bf16 dynsm[];
  bf16* As = dynsm;
  bf16* Bs = dynsm + GST * GTA;

  const bf16* A;
  const bf16* B;
  const float* res;
  void* C;
  int kbase, Kc;
  if (kc > 0) {
    A = A1; B = B1; res = nullptr;
    C = (char*)C1 + (size_t)blockIdx.z * CT * N * 4;
    kbase = blockIdx.z * kc;
    Kc = kc;
  } else {
    A = blockIdx.z ? A2 : A1;
    B = blockIdx.z ? B2 : B1;
    res = blockIdx.z ? res2 : res1;
    C = blockIdx.z ? C2 : C1;
    kbase = 0;
    Kc = K;
  }

  const int tid = threadIdx.x;
  const int lane = tid & 31, warp = tid >> 5;
  const int wm = (warp & 1) * 64, wn = (warp >> 1) * WN;
  const int bm = blockIdx.y * 128, bn = blockIdx.x * BN;
  const int gi = lane >> 2, ti = lane & 3;

  // A load mapping: 2 granules/thread (rows 0..127, cols 32)
  const int agrow = tid >> 1;
  const int agcol = (tid & 1) * 16;
  // B load mapping
  const int bgrow = (BN == 128) ? (tid >> 1) : (tid >> 2);
  const int bgcol = (BN == 128) ? ((tid & 1) * 16) : ((tid & 3) * 8);

  float acc[4][NF][4];
#pragma unroll
  for (int i = 0; i < 4; i++)
#pragma unroll
    for (int j = 0; j < NF; j++)
#pragma unroll
      for (int l = 0; l < 4; l++) acc[i][j][l] = 0.f;

  const int nt = Kc >> 5;
  const bf16* gA = &A[(size_t)(bm + agrow) * K + kbase + agcol];
  const bf16* gB = &B[(size_t)(bn + bgrow) * K + kbase + bgcol];
  const int asoff = agrow * 40 + agcol;
  const int bsoff = bgrow * 40 + bgcol;

  auto load_stage = [&](int st, int kt) {
    const int k0 = kt << 5;
    cp16(&As[st * GTA + asoff], gA + k0);
    cp16(&As[st * GTA + asoff + 8], gA + k0 + 8);
    cp16(&Bs[st * GTB + bsoff], gB + k0);
    if (BN == 128) cp16(&Bs[st * GTB + bsoff + 8], gB + k0 + 8);
  };

#pragma unroll
  for (int s = 0; s < GST - 1; s++) {
    load_stage(s, s);
    asm volatile("cp.async.commit_group;" ::: "memory");
  }

  const int arow = wm + (lane & 15);
  const int acol = (lane >> 4) * 8;
  const int g8 = lane >> 3;
  const int nbrow8 = (g8 >> 1) * 8 + (lane & 7);
  const int bcol = (g8 & 1) * 8;

  for (int t = 0; t < nt; t++) {
    asm volatile("cp.async.wait_group %0;" ::"n"(GST - 2) : "memory");
    __syncthreads();
    const int pf = t + GST - 1;
    if (pf < nt) load_stage(pf & (GST - 1), pf);
    asm volatile("cp.async.commit_group;" ::: "memory");

    const int buf = t & (GST - 1);
    bf16* Ab = As + buf * GTA;
    bf16* Bb = Bs + buf * GTB;
#pragma unroll
    for (int ks = 0; ks < 2; ks++) {
      uint32_t a[4][4], b[NB][4];
#pragma unroll
      for (int fm = 0; fm < 4; fm++)
        ldm4(a[fm], &Ab[(arow + fm * 16) * 40 + ks * 16 + acol]);
#pragma unroll
      for (int nb = 0; nb < NB; nb++)
        ldm4(b[nb], &Bb[(wn + nb * 16 + nbrow8) * 40 + ks * 16 + bcol]);
#pragma unroll
      for (int fm = 0; fm < 4; fm++)
#pragma unroll
        for (int fn = 0; fn < NF; fn++)
          mma_bf16(acc[fm][fn], a[fm], &b[fn >> 1][(fn & 1) * 2]);
    }
  }

#pragma unroll
  for (int fm = 0; fm < 4; fm++) {
#pragma unroll
    for (int fn = 0; fn < NF; fn++) {
      const int r = bm + wm + fm * 16 + gi;
      const int c = bn + wn + fn * 8 + ti * 2;
      float v[4] = {acc[fm][fn][0], acc[fm][fn][1], acc[fm][fn][2],
                    acc[fm][fn][3]};
      if (MODE == 0) {
        float* Cf = (float*)C;
        if (res) {
          const float2 r0 = *(const float2*)&res[(size_t)r * N + c];
          const float2 r1 = *(const float2*)&res[(size_t)(r + 8) * N + c];
          v[0] += r0.x; v[1] += r0.y; v[2] += r1.x; v[3] += r1.y;
        }
        *(float2*)&Cf[(size_t)r * N + c] = make_float2(v[0], v[1]);
        *(float2*)&Cf[(size_t)(r + 8) * N + c] = make_float2(v[2], v[3]);
      } else {
        if (MODE == 2) {
#pragma unroll
          for (int l = 0; l < 4; l++) v[l] = v[l] / (1.f + __expf(-v[l]));
        }
        if (MODE == 3) {
          const bf162 a0 = *(const bf162*)&aux[(size_t)r * N + c];
          const bf162 a1 = *(const bf162*)&aux[(size_t)(r + 8) * N + c];
          v[0] *= __bfloat162float(a0.x); v[1] *= __bfloat162float(a0.y);
          v[2] *= __bfloat162float(a1.x); v[3] *= __bfloat162float(a1.y);
        }
        bf16* Cb = (bf16*)C;
        *(bf162*)&Cb[(size_t)r * N + c] = __floats2bfloat162_rn(v[0], v[1]);
        *(bf162*)&Cb[(size_t)(r + 8) * N + c] =
            __floats2bfloat162_rn(v[2], v[3]);
      }
    }
  }
}

#define GSMEM16 (GST * (128 * 40 + 64 * 40) * 2)
#define GSMEM32 (GST * (128 * 40 + 128 * 40) * 2)

__global__ void reduce_sk(const float* __restrict__ part,
                          bf16* __restrict__ out, int MN, int S) {
  const int i = (blockIdx.x * 256 + threadIdx.x) * 4;
  if (i >= MN) return;
  float4 a = *(const float4*)&part[i];
  for (int s = 1; s < S; s++) {
    const float4 p = *(const float4*)&part[(size_t)s * MN + i];
    a.x += p.x; a.y += p.y; a.z += p.z; a.w += p.w;
  }
  *(bf162*)&out[i] = __floats2bfloat162_rn(a.x, a.y);
  *(bf162*)&out[i + 2] = __floats2bfloat162_rn(a.z, a.w);
}

// ---------------------------------------------------------------------------
// Per-head Us projection + optional RoPE (table). fp32 in, bf16 out.
// ---------------------------------------------------------------------------
__global__ void proj_us_rope(const float* __restrict__ P,
                             const float* __restrict__ Us,
                             const float* __restrict__ tC,
                             const float* __restrict__ tS,
                             bf16* __restrict__ out, int pstride, int doRope) {
  const int hh = blockIdx.y;
  const int tg = threadIdx.y;
  const int dh = threadIdx.x;
  const int t0 = blockIdx.x * 32 + tg * 4;
  __shared__ float sUs[64][33];
  __shared__ float sP[32][33];
  const int tid = tg * 32 + dh;
  const float* UsH = Us + (size_t)hh * 64 * 32;
#pragma unroll
  for (int i = tid; i < 64 * 32; i += 256) sUs[i >> 5][i & 31] = UsH[i];
#pragma unroll
  for (int j = 0; j < 4; j++)
    sP[tg * 4 + j][dh] = P[(size_t)(t0 + j) * pstride + hh * 32 + dh];
  __syncthreads();
  float x1[4] = {0.f, 0.f, 0.f, 0.f}, x2[4] = {0.f, 0.f, 0.f, 0.f};
#pragma unroll
  for (int r = 0; r < 32; r++) {
    const float u1 = sUs[dh][r];
    const float u2 = sUs[dh + 32][r];
#pragma unroll
    for (int j = 0; j < 4; j++) {
      const float p = sP[tg * 4 + j][r];
      x1[j] = fmaf(p, u1, x1[j]);
      x2[j] = fmaf(p, u2, x2[j]);
    }
  }
#pragma unroll
  for (int j = 0; j < 4; j++) {
    float o1 = x1[j], o2 = x2[j];
    if (doRope) {
      const float cs = tC[(t0 + j) * 32 + dh];
      const float sn = tS[(t0 + j) * 32 + dh];
      o1 = x1[j] * cs - x2[j] * sn;
      o2 = x2[j] * cs + x1[j] * sn;
    }
    const size_t base = ((size_t)hh * CT + t0 + j) * CDH;
    out[base + dh] = __float2bfloat16(o1);
    out[base + dh + 32] = __float2bfloat16(o2);
  }
}

// ---------------------------------------------------------------------------
// bf16 causal flash attention, FA2-style. Q tile 128 rows, 8 warps x 16 rows.
// ---------------------------------------------------------------------------
#define FTS2 72
__global__ __launch_bounds__(256) void flash_attn_bf(
    const bf16* __restrict__ Q, const bf16* __restrict__ Kg,
    const bf16* __restrict__ Vg, bf16* __restrict__ Og) {
  __shared__ bf16 Qs[128 * FTS2];
  __shared__ bf16 Ks[64 * FTS2];
  __shared__ bf16 Vt[64 * FTS2];

  const int qb = blockIdx.x, hh = blockIdx.y, hk = hh >> 2;
  const int tid = threadIdx.x;
  const int lane = tid & 31, warp = tid >> 5;
  const int gi = lane >> 2, ti = lane & 3;
  const int wm = warp * 16;
  const int ldr = tid >> 3, c8 = (tid & 7) * 8;

#pragma unroll
  for (int r = 0; r < 4; r++) {
    const int row = ldr + r * 32;
    *(float4*)&Qs[row * FTS2 + c8] =
        *(const float4*)&Q[((size_t)hh * CT + qb * 128 + row) * 64 + c8];
  }
  __syncthreads();

  const int arow_ = wm + (lane & 15);
  const int acol = (lane >> 4) * 8;
  uint32_t aq[4][4];
#pragma unroll
  for (int ks = 0; ks < 4; ks++)
    ldm4(aq[ks], &Qs[arow_ * FTS2 + ks * 16 + acol]);

  const int g8 = lane >> 3;
  const int nbrow = (g8 >> 1) * 8 + (lane & 7);
  const int bcol = (g8 & 1) * 8;

  float m0 = -1e30f, m1 = -1e30f, l0 = 0.f, l1 = 0.f;
  float oacc[8][4];
#pragma unroll
  for (int i = 0; i < 8; i++)
#pragma unroll
    for (int j = 0; j < 4; j++) oacc[i][j] = 0.f;

  const int row0 = qb * 128 + wm + gi;
  const int kbmax = 2 * qb + 1;

  for (int kb = 0; kb <= kbmax; kb++) {
    __syncthreads();
#pragma unroll
    for (int r = 0; r < 2; r++) {
      const int row = ldr + r * 32;
      const size_t gbase = ((size_t)hk * CT + kb * 64 + row) * 64 + c8;
      *(float4*)&Ks[row * FTS2 + c8] = *(const float4*)&Kg[gbase];
      const uint4 vv = *(const uint4*)&Vg[gbase];
      const bf16* pv = (const bf16*)&vv;
#pragma unroll
      for (int j = 0; j < 8; j++) Vt[(c8 + j) * FTS2 + row] = pv[j];
    }
    __syncthreads();

    float sacc[8][4];
#pragma unroll
    for (int i = 0; i < 8; i++)
#pragma unroll
      for (int j = 0; j < 4; j++) sacc[i][j] = 0.f;
#pragma unroll
    for (int ks = 0; ks < 4; ks++) {
      uint32_t b[4][4];
#pragma unroll
      for (int nb = 0; nb < 4; nb++)
        ldm4(b[nb], &Ks[(nbrow + nb * 16) * FTS2 + ks * 16 + bcol]);
#pragma unroll
      for (int fn = 0; fn < 8; fn++)
        mma_bf16(sacc[fn], aq[ks], &b[fn >> 1][(fn & 1) * 2]);
    }

    const bool needMask = (kb * 64 + 63) > row0;
    float rmax0 = -1e30f, rmax1 = -1e30f;
#pragma unroll
    for (int fn = 0; fn < 8; fn++) {
      const int c = kb * 64 + fn * 8 + 2 * ti;
#pragma unroll
      for (int l = 0; l < 4; l++) {
        float v = sacc[fn][l] * 0.125f;
        if (needMask) {
          const int row = row0 + ((l >= 2) ? 8 : 0);
          if (c + (l & 1) > row) v = -1e30f;
        }
        sacc[fn][l] = v;
        if (l >= 2) rmax1 = fmaxf(rmax1, v);
        else rmax0 = fmaxf(rmax0, v);
      }
    }
    rmax0 = fmaxf(rmax0, __shfl_xor_sync(0xffffffffu, rmax0, 1));
    rmax0 = fmaxf(rmax0, __shfl_xor_sync(0xffffffffu, rmax0, 2));
    rmax1 = fmaxf(rmax1, __shfl_xor_sync(0xffffffffu, rmax1, 1));
    rmax1 = fmaxf(rmax1, __shfl_xor_sync(0xffffffffu, rmax1, 2));
    const float mn0 = fmaxf(m0, rmax0), mn1 = fmaxf(m1, rmax1);
    const float al0 = __expf(m0 - mn0), al1 = __expf(m1 - mn1);
    m0 = mn0; m1 = mn1;

    float rs0 = 0.f, rs1 = 0.f;
    uint32_t ap[4][4];
#pragma unroll
    for (int ks = 0; ks < 4; ks++) {
      const int f0 = 2 * ks, f1 = 2 * ks + 1;
      const float p00 = __expf(sacc[f0][0] - m0);
      const float p01 = __expf(sacc[f0][1] - m0);
      const float p02 = __expf(sacc[f0][2] - m1);
      const float p03 = __expf(sacc[f0][3] - m1);
      const float p10 = __expf(sacc[f1][0] - m0);
      const float p11 = __expf(sacc[f1][1] - m0);
      const float p12 = __expf(sacc[f1][2] - m1);
      const float p13 = __expf(sacc[f1][3] - m1);
      rs0 += p00 + p01 + p10 + p11;
      rs1 += p02 + p03 + p12 + p13;
      ap[ks][0] = packbf(p00, p01);
      ap[ks][1] = packbf(p02, p03);
      ap[ks][2] = packbf(p10, p11);
      ap[ks][3] = packbf(p12, p13);
    }
    rs0 += __shfl_xor_sync(0xffffffffu, rs0, 1);
    rs0 += __shfl_xor_sync(0xffffffffu, rs0, 2);
    rs1 += __shfl_xor_sync(0xffffffffu, rs1, 1);
    rs1 += __shfl_xor_sync(0xffffffffu, rs1, 2);
    l0 = l0 * al0 + rs0;
    l1 = l1 * al1 + rs1;
#pragma unroll
    for (int fn = 0; fn < 8; fn++) {
      oacc[fn][0] *= al0; oacc[fn][1] *= al0;
      oacc[fn][2] *= al1; oacc[fn][3] *= al1;
    }

#pragma unroll
    for (int ks = 0; ks < 4; ks++) {
      uint32_t b[4][4];
#pragma unroll
      for (int nb = 0; nb < 4; nb++)
        ldm4(b[nb], &Vt[(nbrow + nb * 16) * FTS2 + ks * 16 + bcol]);
#pragma unroll
      for (int fn = 0; fn < 8; fn++)
        mma_bf16(oacc[fn], ap[ks], &b[fn >> 1][(fn & 1) * 2]);
    }
  }

  const float inv0 = 1.f / l0, inv1 = 1.f / l1;
#pragma unroll
  for (int fn = 0; fn < 8; fn++) {
    const int col = hh * 64 + fn * 8 + 2 * ti;
    *(bf162*)&Og[(size_t)(row0) * CD + col] =
        __floats2bfloat162_rn(oacc[fn][0] * inv0, oacc[fn][1] * inv0);
    *(bf162*)&Og[(size_t)(row0 + 8) * CD + col] =
        __floats2bfloat162_rn(oacc[fn][2] * inv1, oacc[fn][3] * inv1);
  }
}

// ---------------------------------------------------------------------------
// Launch pipeline
// ---------------------------------------------------------------------------
extern "C" void kernel_launch(void* const* d_in, const int* in_sizes, int n_in,
                              void* d_out, int out_size) {
  const float* hidden = (const float*)d_in[0];
  const float* ln1 = (const float*)d_in[1];
  const float* ln2 = (const float*)d_in[2];
  const float* q_Us = (const float*)d_in[3];
  const float* q_V  = (const float*)d_in[4];
  const float* k_Us = (const float*)d_in[5];
  const float* k_V  = (const float*)d_in[6];
  const float* v_Us = (const float*)d_in[7];
  const float* v_V  = (const float*)d_in[8];
  const float* o_Us = (const float*)d_in[9];
  const float* o_V  = (const float*)d_in[10];
  const float* g_Us = (const float*)d_in[11];
  const float* g_V  = (const float*)d_in[12];
  const float* u_Us = (const float*)d_in[13];
  const float* u_V  = (const float*)d_in[14];
  const float* d_Us = (const float*)d_in[15];
  const float* d_V  = (const float*)d_in[16];
  float* out = (float*)d_out;

  Scratch* s = nullptr;
  cudaGetSymbolAddress((void**)&s, g_scratch);

  cudaFuncSetAttribute(gemm_bf<0, 16>,
                       cudaFuncAttributeMaxDynamicSharedMemorySize, GSMEM16);
  cudaFuncSetAttribute(gemm_bf<1, 16>,
                       cudaFuncAttributeMaxDynamicSharedMemorySize, GSMEM16);
  cudaFuncSetAttribute(gemm_bf<2, 32>,
                       cudaFuncAttributeMaxDynamicSharedMemorySize, GSMEM32);
  cudaFuncSetAttribute(gemm_bf<3, 32>,
                       cudaFuncAttributeMaxDynamicSharedMemorySize, GSMEM32);

  // 0. weight conversion + rope table
  {
    CvtPack p;
    const float* srcs[NCVT] = {q_V, k_V, v_V, o_Us, o_V, g_Us,
                               g_V, u_Us, u_V, d_Us, d_V};
    bf16* dsts[NCVT] = {s->qV, s->kV, s->vV, s->oUs, s->oV, s->gUs,
                        s->gV, s->uUs, s->uV, s->dUs, s->dV};
    const int ns[NCVT] = {1024 * CD, 256 * CD, 256 * CD, CD * 512, 512 * CD,
                          CINTER * 512, 512 * CD, CINTER * 512, 512 * CD,
                          CD * 512, 512 * CINTER};
    int total4 = 0;
    for (int i = 0; i < NCVT; i++) {
      p.src[i] = srcs[i]; p.dst[i] = dsts[i]; p.n4[i] = ns[i] / 4;
      total4 += ns[i] / 4;
    }
    cvt_f2bf<<<(total4 + 255) / 256, 256>>>(p, total4);
  }
  rope_tab<<<CT * 32 / 256, 256>>>(s->ropeC, s->ropeS);

  // 1. x = rmsnorm(hidden, ln1)
  rmsnorm_bf<<<CT, 256>>>(hidden, ln1, s->x);

  // 2. fused QKV low-rank projection (fp32 out)
  gemm_bf<0, 16><<<dim3(24, 16, 1), 256, GSMEM16>>>(
      s->x, s->qV, nullptr, s->Pqkv, nullptr, nullptr, nullptr, nullptr,
      nullptr, 1536, CD, 0);

  // 3. Us up-projections + RoPE
  proj_us_rope<<<dim3(CT / 32, CH), dim3(32, 8)>>>(
      s->Pqkv, q_Us, s->ropeC, s->ropeS, s->q, 1536, 1);
  proj_us_rope<<<dim3(CT / 32, CHK), dim3(32, 8)>>>(
      s->Pqkv + 1024, k_Us, s->ropeC, s->ropeS, s->k, 1536, 1);
  proj_us_rope<<<dim3(CT / 32, CHK), dim3(32, 8)>>>(
      s->Pqkv + 1280, v_Us, s->ropeC, s->ropeS, s->v, 1536, 0);

  // 4. attention
  flash_attn_bf<<<dim3(CT / 128, CH), 256>>>(s->q, s->k, s->v, s->attn);

  // 5. output projection (split-K=2) + residual -> h
  gemm_bf<0, 16><<<dim3(8, 16, 2), 256, GSMEM16>>>(
      s->attn, s->oV, nullptr, s->skpart, nullptr, nullptr, nullptr, nullptr,
      nullptr, 512, CD, 1024);
  reduce_sk<<<CT * 512 / 1024, 256>>>(s->skpart, s->Po, CT * 512, 2);
  gemm_bf<0, 16><<<dim3(32, 16, 1), 256, GSMEM16>>>(
      s->Po, s->oUs, hidden, s->h, nullptr, nullptr, nullptr, nullptr,
      nullptr, CD, 512, 0);

  // 6. FFN
  rmsnorm_bf<<<CT, 256>>>(s->h, ln2, s->x);
  gemm_bf<1, 16><<<dim3(8, 16, 2), 256, GSMEM16>>>(
      s->x, s->gV, nullptr, s->Pg, s->x, s->uV, nullptr, s->Pu,
      nullptr, 512, CD, 0);
  gemm_bf<2, 32><<<dim3(64, 16, 1), 256, GSMEM32>>>(
      s->Pg, s->gUs, nullptr, s->gate, nullptr, nullptr, nullptr, nullptr,
      nullptr, CINTER, 512, 0);
  gemm_bf<3, 32><<<dim3(64, 16, 1), 256, GSMEM32>>>(
      s->Pu, s->uUs, nullptr, s->up, nullptr, nullptr, nullptr, nullptr,
      s->gate, CINTER, 512, 0);
  gemm_bf<0, 16><<<dim3(8, 16, 4), 256, GSMEM16>>>(
      s->up, s->dV, nullptr, s->skpart, nullptr, nullptr, nullptr, nullptr,
      nullptr, 512, CINTER, 2048);
  reduce_sk<<<CT * 512 / 1024, 256>>>(s->skpart, s->Pd, CT * 512, 4);
  gemm_bf<0, 16><<<dim3(32, 16, 1), 256, GSMEM16>>>(
      s->Pd, s->dUs, s->h, out, nullptr, nullptr, nullptr, nullptr,
      nullptr, CD, 512, 0);
}

// round 12
// speedup vs baseline: 1.1296x; 1.1296x over previous
#include <cuda_runtime.h>
#include <cuda_bf16.h>
#include <math.h>
#include <cstdint>

#define CT 2048
#define CD 2048
#define CH 32
#define CHK 8
#define CDH 64
#define CINTER 8192

typedef __nv_bfloat16 bf16;
typedef __nv_bfloat162 bf162;

// ---------------------------------------------------------------------------
// Static device scratch
// ---------------------------------------------------------------------------
struct alignas(256) Scratch {
  float Pqkv[CT * 1536];
  float h[CT * CD];
  float skpart[4 * CT * 512];
  float ropeC[CT * 32];
  float ropeS[CT * 32];
  bf16 x[CT * CD];
  bf16 q[CH * CT * CDH];
  bf16 k[CHK * CT * CDH];
  bf16 v[CHK * CT * CDH];
  bf16 attn[CT * CD];
  bf16 Po[CT * 512];
  bf16 Pg[CT * 512];
  bf16 Pu[CT * 512];
  bf16 gate[CT * CINTER];
  bf16 up[CT * CINTER];
  bf16 Pd[CT * 512];
  bf16 qV[1024 * CD];
  bf16 kV[256 * CD];
  bf16 vV[256 * CD];
  bf16 oUs[CD * 512];
  bf16 oV[512 * CD];
  bf16 gUs[CINTER * 512];
  bf16 gV[512 * CD];
  bf16 uUs[CINTER * 512];
  bf16 uV[512 * CD];
  bf16 dUs[CD * 512];
  bf16 dV[512 * CINTER];
};
__device__ Scratch g_scratch;

// ---------------------------------------------------------------------------
// helpers
// ---------------------------------------------------------------------------
__device__ __forceinline__ void cp16(void* s, const void* g) {
  uint32_t sa = (uint32_t)__cvta_generic_to_shared(s);
  asm volatile("cp.async.cg.shared.global [%0], [%1], 16;" ::"r"(sa), "l"(g));
}
__device__ __forceinline__ void mma_bf16(float* c, const uint32_t* a,
                                         const uint32_t* b) {
  asm volatile(
      "mma.sync.aligned.m16n8k16.row.col.f32.bf16.bf16.f32 "
      "{%0,%1,%2,%3}, {%4,%5,%6,%7}, {%8,%9}, {%0,%1,%2,%3};"
      : "+f"(c[0]), "+f"(c[1]), "+f"(c[2]), "+f"(c[3])
      : "r"(a[0]), "r"(a[1]), "r"(a[2]), "r"(a[3]), "r"(b[0]), "r"(b[1]));
}
__device__ __forceinline__ void ldm4(uint32_t* r, const void* p) {
  uint32_t a = (uint32_t)__cvta_generic_to_shared(p);
  asm volatile(
      "ldmatrix.sync.aligned.m8n8.x4.shared.b16 {%0,%1,%2,%3}, [%4];"
      : "=r"(r[0]), "=r"(r[1]), "=r"(r[2]), "=r"(r[3])
      : "r"(a));
}
__device__ __forceinline__ void ldm4t(uint32_t* r, const void* p) {
  uint32_t a = (uint32_t)__cvta_generic_to_shared(p);
  asm volatile(
      "ldmatrix.sync.aligned.m8n8.x4.trans.shared.b16 {%0,%1,%2,%3}, [%4];"
      : "=r"(r[0]), "=r"(r[1]), "=r"(r[2]), "=r"(r[3])
      : "r"(a));
}
__device__ __forceinline__ uint32_t packbf(float a, float b) {
  bf162 v = __floats2bfloat162_rn(a, b);
  return *(uint32_t*)&v;
}

// ---------------------------------------------------------------------------
// weight conversion fp32 -> bf16
// ---------------------------------------------------------------------------
#define NCVT 11
struct CvtPack {
  const float* src[NCVT];
  bf16* dst[NCVT];
  int n4[NCVT];
};
__global__ void cvt_f2bf(CvtPack p, int total4) {
  int i = blockIdx.x * 256 + threadIdx.x;
  if (i >= total4) return;
  int s = 0, off = i;
  while (off >= p.n4[s]) { off -= p.n4[s]; s++; }
  const float4 v = ((const float4*)p.src[s])[off];
  bf162* d = (bf162*)p.dst[s];
  d[off * 2] = __floats2bfloat162_rn(v.x, v.y);
  d[off * 2 + 1] = __floats2bfloat162_rn(v.z, v.w);
}

__global__ void rope_tab(float* __restrict__ c, float* __restrict__ s) {
  const int i = blockIdx.x * 256 + threadIdx.x;
  const int t = i >> 5, d = i & 31;
  const float invf = exp2f(-0.41524101186092028f * (float)d);
  float sn, cs;
  sincosf((float)t * invf, &sn, &cs);
  c[i] = cs;
  s[i] = sn;
}

// ---------------------------------------------------------------------------
// RMSNorm (fp32 in, bf16 out)
// ---------------------------------------------------------------------------
__global__ void rmsnorm_bf(const float* __restrict__ in,
                           const float* __restrict__ w,
                           bf16* __restrict__ out) {
  const int t = blockIdx.x;
  const float* row = in + (size_t)t * CD;
  float ss = 0.f;
  for (int i = threadIdx.x; i < CD; i += 256) {
    float v = row[i];
    ss += v * v;
  }
  __shared__ float red[8];
#pragma unroll
  for (int o = 16; o > 0; o >>= 1) ss += __shfl_xor_sync(0xffffffffu, ss, o);
  if ((threadIdx.x & 31) == 0) red[threadIdx.x >> 5] = ss;
  __syncthreads();
  if (threadIdx.x == 0) {
    float v = 0.f;
#pragma unroll
    for (int i = 0; i < 8; i++) v += red[i];
    red[0] = v;
  }
  __syncthreads();
  const float inv = rsqrtf(red[0] * (1.0f / CD) + 1e-5f);
  for (int i = threadIdx.x * 2; i < CD; i += 512) {
    bf162 o = __floats2bfloat162_rn(row[i] * inv * w[i],
                                    row[i + 1] * inv * w[i + 1]);
    *(bf162*)&out[(size_t)t * CD + i] = o;
  }
}

// ---------------------------------------------------------------------------
// bf16 GEMM (NT), 4-stage cp.async pipeline. 128x128x32 tiles (R7 config).
// MODE 0: fp32 out (+res). 1: bf16. 2: bf16 silu. 3: bf16 *aux.
// kc>0: split-K; else blockIdx.z picks problem pair.
// ---------------------------------------------------------------------------
#define GST 4
#define GTILE (128 * 40)
#define GSMEM (2 * GST * GTILE * 2)

template <int MODE>
__global__ __launch_bounds__(256, 2) void gemm_bf(
    const bf16* __restrict__ A1, const bf16* __restrict__ B1,
    const float* __restrict__ res1, void* __restrict__ C1,
    const bf16* __restrict__ A2, const bf16* __restrict__ B2,
    const float* __restrict__ res2, void* __restrict__ C2,
    const bf16* __restrict__ aux, int N, int K, int kc) {
  extern __shared__ bf16 dynsm[];
  bf16* As = dynsm;
  bf16* Bs = dynsm + GST * GTILE;

  const bf16* A;
  const bf16* B;
  const float* res;
  void* C;
  int kbase, Kc;
  if (kc > 0) {
    A = A1; B = B1; res = nullptr;
    C = (char*)C1 + (size_t)blockIdx.z * CT * N * 4;
    kbase = blockIdx.z * kc;
    Kc = kc;
  } else {
    A = blockIdx.z ? A2 : A1;
    B = blockIdx.z ? B2 : B1;
    res = blockIdx.z ? res2 : res1;
    C = blockIdx.z ? C2 : C1;
    kbase = 0;
    Kc = K;
  }

  const int tid = threadIdx.x;
  const int lane = tid & 31, warp = tid >> 5;
  const int wm = (warp & 1) * 64, wn = (warp >> 1) * 32;
  const int bm = blockIdx.y * 128, bn = blockIdx.x * 128;
  const int gi = lane >> 2, ti = lane & 3;
  const int grow = tid >> 1;
  const int gcol = (tid & 1) * 16;

  float acc[4][4][4];
#pragma unroll
  for (int i = 0; i < 4; i++)
#pragma unroll
    for (int j = 0; j < 4; j++)
#pragma unroll
      for (int l = 0; l < 4; l++) acc[i][j][l] = 0.f;

  const int nt = Kc >> 5;
  const bf16* gA = &A[(size_t)(bm + grow) * K + kbase + gcol];
  const bf16* gB = &B[(size_t)(bn + grow) * K + kbase + gcol];
  const int soff = grow * 40 + gcol;

  auto load_stage = [&](int st, int kt) {
    const int k0 = kt << 5;
    cp16(&As[st * GTILE + soff], gA + k0);
    cp16(&As[st * GTILE + soff + 8], gA + k0 + 8);
    cp16(&Bs[st * GTILE + soff], gB + k0);
    cp16(&Bs[st * GTILE + soff + 8], gB + k0 + 8);
  };

#pragma unroll
  for (int s = 0; s < GST - 1; s++) {
    load_stage(s, s);
    asm volatile("cp.async.commit_group;" ::: "memory");
  }

  const int arow = wm + (lane & 15);
  const int acol = (lane >> 4) * 8;
  const int g8 = lane >> 3;
  const int brow = wn + (g8 >> 1) * 8 + (lane & 7);
  const int bcol = (g8 & 1) * 8;

  for (int t = 0; t < nt; t++) {
    asm volatile("cp.async.wait_group %0;" ::"n"(GST - 2) : "memory");
    __syncthreads();
    const int pf = t + GST - 1;
    if (pf < nt) load_stage(pf & (GST - 1), pf);
    asm volatile("cp.async.commit_group;" ::: "memory");

    const int buf = t & (GST - 1);
    bf16* Ab = As + buf * GTILE;
    bf16* Bb = Bs + buf * GTILE;
#pragma unroll
    for (int ks = 0; ks < 2; ks++) {
      uint32_t a[4][4], b[2][4];
#pragma unroll
      for (int fm = 0; fm < 4; fm++)
        ldm4(a[fm], &Ab[(arow + fm * 16) * 40 + ks * 16 + acol]);
      ldm4(b[0], &Bb[brow * 40 + ks * 16 + bcol]);
      ldm4(b[1], &Bb[(brow + 16) * 40 + ks * 16 + bcol]);
#pragma unroll
      for (int fm = 0; fm < 4; fm++)
#pragma unroll
        for (int fn = 0; fn < 4; fn++)
          mma_bf16(acc[fm][fn], a[fm], &b[fn >> 1][(fn & 1) * 2]);
    }
  }

#pragma unroll
  for (int fm = 0; fm < 4; fm++) {
#pragma unroll
    for (int fn = 0; fn < 4; fn++) {
      const int r = bm + wm + fm * 16 + gi;
      const int c = bn + wn + fn * 8 + ti * 2;
      float v[4] = {acc[fm][fn][0], acc[fm][fn][1], acc[fm][fn][2],
                    acc[fm][fn][3]};
      if (MODE == 0) {
        float* Cf = (float*)C;
        if (res) {
          const float2 r0 = *(const float2*)&res[(size_t)r * N + c];
          const float2 r1 = *(const float2*)&res[(size_t)(r + 8) * N + c];
          v[0] += r0.x; v[1] += r0.y; v[2] += r1.x; v[3] += r1.y;
        }
        *(float2*)&Cf[(size_t)r * N + c] = make_float2(v[0], v[1]);
        *(float2*)&Cf[(size_t)(r + 8) * N + c] = make_float2(v[2], v[3]);
      } else {
        if (MODE == 2) {
#pragma unroll
          for (int l = 0; l < 4; l++) v[l] = v[l] / (1.f + __expf(-v[l]));
        }
        if (MODE == 3) {
          const bf162 a0 = *(const bf162*)&aux[(size_t)r * N + c];
          const bf162 a1 = *(const bf162*)&aux[(size_t)(r + 8) * N + c];
          v[0] *= __bfloat162float(a0.x); v[1] *= __bfloat162float(a0.y);
          v[2] *= __bfloat162float(a1.x); v[3] *= __bfloat162float(a1.y);
        }
        bf16* Cb = (bf16*)C;
        *(bf162*)&Cb[(size_t)r * N + c] = __floats2bfloat162_rn(v[0], v[1]);
        *(bf162*)&Cb[(size_t)(r + 8) * N + c] =
            __floats2bfloat162_rn(v[2], v[3]);
      }
    }
  }
}

__global__ void reduce_sk(const float* __restrict__ part,
                          bf16* __restrict__ out, int MN, int S) {
  const int i = (blockIdx.x * 256 + threadIdx.x) * 4;
  if (i >= MN) return;
  float4 a = *(const float4*)&part[i];
  for (int s = 1; s < S; s++) {
    const float4 p = *(const float4*)&part[(size_t)s * MN + i];
    a.x += p.x; a.y += p.y; a.z += p.z; a.w += p.w;
  }
  *(bf162*)&out[i] = __floats2bfloat162_rn(a.x, a.y);
  *(bf162*)&out[i + 2] = __floats2bfloat162_rn(a.z, a.w);
}

// ---------------------------------------------------------------------------
// Per-head Us projection + optional RoPE (table). fp32 in, bf16 out.
// ---------------------------------------------------------------------------
__global__ void proj_us_rope(const float* __restrict__ P,
                             const float* __restrict__ Us,
                             const float* __restrict__ tC,
                             const float* __restrict__ tS,
                             bf16* __restrict__ out, int pstride, int doRope) {
  const int hh = blockIdx.y;
  const int tg = threadIdx.y;
  const int dh = threadIdx.x;
  const int t0 = blockIdx.x * 32 + tg * 4;
  __shared__ float sUs[64][33];
  __shared__ float sP[32][33];
  const int tid = tg * 32 + dh;
  const float* UsH = Us + (size_t)hh * 64 * 32;
#pragma unroll
  for (int i = tid; i < 64 * 32; i += 256) sUs[i >> 5][i & 31] = UsH[i];
#pragma unroll
  for (int j = 0; j < 4; j++)
    sP[tg * 4 + j][dh] = P[(size_t)(t0 + j) * pstride + hh * 32 + dh];
  __syncthreads();
  float x1[4] = {0.f, 0.f, 0.f, 0.f}, x2[4] = {0.f, 0.f, 0.f, 0.f};
#pragma unroll
  for (int r = 0; r < 32; r++) {
    const float u1 = sUs[dh][r];
    const float u2 = sUs[dh + 32][r];
#pragma unroll
    for (int j = 0; j < 4; j++) {
      const float p = sP[tg * 4 + j][r];
      x1[j] = fmaf(p, u1, x1[j]);
      x2[j] = fmaf(p, u2, x2[j]);
    }
  }
#pragma unroll
  for (int j = 0; j < 4; j++) {
    float o1 = x1[j], o2 = x2[j];
    if (doRope) {
      const float cs = tC[(t0 + j) * 32 + dh];
      const float sn = tS[(t0 + j) * 32 + dh];
      o1 = x1[j] * cs - x2[j] * sn;
      o2 = x2[j] * cs + x1[j] * sn;
    }
    const size_t base = ((size_t)hh * CT + t0 + j) * CDH;
    out[base + dh] = __float2bfloat16(o1);
    out[base + dh + 32] = __float2bfloat16(o2);
  }
}

// ---------------------------------------------------------------------------
// bf16 causal flash attention, FA2-style. Q tile 128 rows, 8 warps x 16 rows.
// V fed via ldmatrix.trans (no scalar transpose); K/V cp.async double-buffered.
// ---------------------------------------------------------------------------
#define FTS2 72
#define FA_Q_FLOATS (128 * FTS2)
#define FA_KV_FLOATS (64 * FTS2)
#define FA_SMEM_B ((FA_Q_FLOATS + 4 * FA_KV_FLOATS) * 2)
__global__ __launch_bounds__(256) void flash_attn_bf(
    const bf16* __restrict__ Q, const bf16* __restrict__ Kg,
    const bf16* __restrict__ Vg, bf16* __restrict__ Og) {
  extern __shared__ bf16 fasm[];
  bf16* Qs = fasm;                       // [128][FTS2]
  bf16* Ks = fasm + FA_Q_FLOATS;         // [2][64][FTS2]
  bf16* Vs = Ks + 2 * FA_KV_FLOATS;      // [2][64][FTS2] row-major [kv][dh]

  const int qb = blockIdx.x, hh = blockIdx.y, hk = hh >> 2;
  const int tid = threadIdx.x;
  const int lane = tid & 31, warp = tid >> 5;
  const int gi = lane >> 2, ti = lane & 3;
  const int wm = warp * 16;
  const int ldr = tid >> 3, c8 = (tid & 7) * 8;

  // load Q (128x64) via cp.async
#pragma unroll
  for (int r = 0; r < 4; r++) {
    const int row = ldr + r * 32;
    cp16(&Qs[row * FTS2 + c8],
         &Q[((size_t)hh * CT + qb * 128 + row) * 64 + c8]);
  }
  asm volatile("cp.async.commit_group;" ::: "memory");

  // kv tile loader (rows ldr, ldr+32)
  auto load_kv = [&](int buf, int kb) {
    bf16* kd = Ks + buf * FA_KV_FLOATS;
    bf16* vd = Vs + buf * FA_KV_FLOATS;
#pragma unroll
    for (int r = 0; r < 2; r++) {
      const int row = ldr + r * 32;
      const size_t gbase = ((size_t)hk * CT + kb * 64 + row) * 64 + c8;
      cp16(&kd[row * FTS2 + c8], &Kg[gbase]);
      cp16(&vd[row * FTS2 + c8], &Vg[gbase]);
    }
  };

  load_kv(0, 0);
  asm volatile("cp.async.commit_group;" ::: "memory");

  // wait Q + tile0
  asm volatile("cp.async.wait_group 0;" ::: "memory");
  __syncthreads();

  // Q fragments -> registers
  const int arow_ = wm + (lane & 15);
  const int acol = (lane >> 4) * 8;
  uint32_t aq[4][4];
#pragma unroll
  for (int ks = 0; ks < 4; ks++)
    ldm4(aq[ks], &Qs[arow_ * FTS2 + ks * 16 + acol]);

  const int g8 = lane >> 3;
  const int nbrow = (g8 >> 1) * 8 + (lane & 7);   // K: n-row within 16
  const int bcol = (g8 & 1) * 8;                  // K: k-col offset
  const int tkrow = (g8 & 1) * 8 + (lane & 7);    // V-trans: k-row within 16
  const int tncol = (g8 >> 1) * 8;                // V-trans: n-col offset

  float m0 = -1e30f, m1 = -1e30f, l0 = 0.f, l1 = 0.f;
  float oacc[8][4];
#pragma unroll
  for (int i = 0; i < 8; i++)
#pragma unroll
    for (int j = 0; j < 4; j++) oacc[i][j] = 0.f;

  const int row0 = qb * 128 + wm + gi;
  const int kbmax = 2 * qb + 1;

  for (int kb = 0; kb <= kbmax; kb++) {
    const int buf = kb & 1;
    if (kb > 0) {
      asm volatile("cp.async.wait_group 0;" ::: "memory");
    }
    __syncthreads();  // tile kb visible to all; prev compute done on buf^1
    if (kb < kbmax) {
      load_kv(buf ^ 1, kb + 1);
      asm volatile("cp.async.commit_group;" ::: "memory");
    }
    bf16* Kb = Ks + buf * FA_KV_FLOATS;
    bf16* Vb = Vs + buf * FA_KV_FLOATS;

    // S = Q K^T
    float sacc[8][4];
#pragma unroll
    for (int i = 0; i < 8; i++)
#pragma unroll
      for (int j = 0; j < 4; j++) sacc[i][j] = 0.f;
#pragma unroll
    for (int ks = 0; ks < 4; ks++) {
      uint32_t b[4][4];
#pragma unroll
      for (int nb = 0; nb < 4; nb++)
        ldm4(b[nb], &Kb[(nbrow + nb * 16) * FTS2 + ks * 16 + bcol]);
#pragma unroll
      for (int fn = 0; fn < 8; fn++)
        mma_bf16(sacc[fn], aq[ks], &b[fn >> 1][(fn & 1) * 2]);
    }

    // scale + mask + warp-local softmax
    const bool needMask = (kb * 64 + 63) > row0;
    float rmax0 = -1e30f, rmax1 = -1e30f;
#pragma unroll
    for (int fn = 0; fn < 8; fn++) {
      const int c = kb * 64 + fn * 8 + 2 * ti;
#pragma unroll
      for (int l = 0; l < 4; l++) {
        float v = sacc[fn][l] * 0.125f;
        if (needMask) {
          const int row = row0 + ((l >= 2) ? 8 : 0);
          if (c + (l & 1) > row) v = -1e30f;
        }
        sacc[fn][l] = v;
        if (l >= 2) rmax1 = fmaxf(rmax1, v);
        else rmax0 = fmaxf(rmax0, v);
      }
    }
    rmax0 = fmaxf(rmax0, __shfl_xor_sync(0xffffffffu, rmax0, 1));
    rmax0 = fmaxf(rmax0, __shfl_xor_sync(0xffffffffu, rmax0, 2));
    rmax1 = fmaxf(rmax1, __shfl_xor_sync(0xffffffffu, rmax1, 1));
    rmax1 = fmaxf(rmax1, __shfl_xor_sync(0xffffffffu, rmax1, 2));
    const float mn0 = fmaxf(m0, rmax0), mn1 = fmaxf(m1, rmax1);
    const float al0 = __expf(m0 - mn0), al1 = __expf(m1 - mn1);
    m0 = mn0; m1 = mn1;

    float rs0 = 0.f, rs1 = 0.f;
    uint32_t ap[4][4];
#pragma unroll
    for (int ks = 0; ks < 4; ks++) {
      const int f0 = 2 * ks, f1 = 2 * ks + 1;
      const float p00 = __expf(sacc[f0][0] - m0);
      const float p01 = __expf(sacc[f0][1] - m0);
      const float p02 = __expf(sacc[f0][2] - m1);
      const float p03 = __expf(sacc[f0][3] - m1);
      const float p10 = __expf(sacc[f1][0] - m0);
      const float p11 = __expf(sacc[f1][1] - m0);
      const float p12 = __expf(sacc[f1][2] - m1);
      const float p13 = __expf(sacc[f1][3] - m1);
      rs0 += p00 + p01 + p10 + p11;
      rs1 += p02 + p03 + p12 + p13;
      ap[ks][0] = packbf(p00, p01);
      ap[ks][1] = packbf(p02, p03);
      ap[ks][2] = packbf(p10, p11);
      ap[ks][3] = packbf(p12, p13);
    }
    rs0 += __shfl_xor_sync(0xffffffffu, rs0, 1);
    rs0 += __shfl_xor_sync(0xffffffffu, rs0, 2);
    rs1 += __shfl_xor_sync(0xffffffffu, rs1, 1);
    rs1 += __shfl_xor_sync(0xffffffffu, rs1, 2);
    l0 = l0 * al0 + rs0;
    l1 = l1 * al1 + rs1;
#pragma unroll
    for (int fn = 0; fn < 8; fn++) {
      oacc[fn][0] *= al0; oacc[fn][1] *= al0;
      oacc[fn][2] *= al1; oacc[fn][3] *= al1;
    }

    // O += P V : B fragments from row-major V via ldmatrix.trans
#pragma unroll
    for (int ks = 0; ks < 4; ks++) {
      uint32_t b[4][4];
#pragma unroll
      for (int nb = 0; nb < 4; nb++)
        ldm4t(b[nb], &Vb[(ks * 16 + tkrow) * FTS2 + nb * 16 + tncol]);
#pragma unroll
      for (int fn = 0; fn < 8; fn++)
        mma_bf16(oacc[fn], ap[ks], &b[fn >> 1][(fn & 1) * 2]);
    }
  }

  const float inv0 = 1.f / l0, inv1 = 1.f / l1;
#pragma unroll
  for (int fn = 0; fn < 8; fn++) {
    const int col = hh * 64 + fn * 8 + 2 * ti;
    *(bf162*)&Og[(size_t)(row0) * CD + col] =
        __floats2bfloat162_rn(oacc[fn][0] * inv0, oacc[fn][1] * inv0);
    *(bf162*)&Og[(size_t)(row0 + 8) * CD + col] =
        __floats2bfloat162_rn(oacc[fn][2] * inv1, oacc[fn][3] * inv1);
  }
}

// ---------------------------------------------------------------------------
// Launch pipeline
// ---------------------------------------------------------------------------
extern "C" void kernel_launch(void* const* d_in, const int* in_sizes, int n_in,
                              void* d_out, int out_size) {
  const float* hidden = (const float*)d_in[0];
  const float* ln1 = (const float*)d_in[1];
  const float* ln2 = (const float*)d_in[2];
  const float* q_Us = (const float*)d_in[3];
  const float* q_V  = (const float*)d_in[4];
  const float* k_Us = (const float*)d_in[5];
  const float* k_V  = (const float*)d_in[6];
  const float* v_Us = (const float*)d_in[7];
  const float* v_V  = (const float*)d_in[8];
  const float* o_Us = (const float*)d_in[9];
  const float* o_V  = (const float*)d_in[10];
  const float* g_Us = (const float*)d_in[11];
  const float* g_V  = (const float*)d_in[12];
  const float* u_Us = (const float*)d_in[13];
  const float* u_V  = (const float*)d_in[14];
  const float* d_Us = (const float*)d_in[15];
  const float* d_V  = (const float*)d_in[16];
  float* out = (float*)d_out;

  Scratch* s = nullptr;
  cudaGetSymbolAddress((void**)&s, g_scratch);

  cudaFuncSetAttribute(gemm_bf<0>,
                       cudaFuncAttributeMaxDynamicSharedMemorySize, GSMEM);
  cudaFuncSetAttribute(gemm_bf<1>,
                       cudaFuncAttributeMaxDynamicSharedMemorySize, GSMEM);
  cudaFuncSetAttribute(gemm_bf<2>,
                       cudaFuncAttributeMaxDynamicSharedMemorySize, GSMEM);
  cudaFuncSetAttribute(gemm_bf<3>,
                       cudaFuncAttributeMaxDynamicSharedMemorySize, GSMEM);
  cudaFuncSetAttribute(flash_attn_bf,
                       cudaFuncAttributeMaxDynamicSharedMemorySize, FA_SMEM_B);

  // 0. weight conversion + rope table
  {
    CvtPack p;
    const float* srcs[NCVT] = {q_V, k_V, v_V, o_Us, o_V, g_Us,
                               g_V, u_Us, u_V, d_Us, d_V};
    bf16* dsts[NCVT] = {s->qV, s->kV, s->vV, s->oUs, s->oV, s->gUs,
                        s->gV, s->uUs, s->uV, s->dUs, s->dV};
    const int ns[NCVT] = {1024 * CD, 256 * CD, 256 * CD, CD * 512, 512 * CD,
                          CINTER * 512, 512 * CD, CINTER * 512, 512 * CD,
                          CD * 512, 512 * CINTER};
    int total4 = 0;
    for (int i = 0; i < NCVT; i++) {
      p.src[i] = srcs[i]; p.dst[i] = dsts[i]; p.n4[i] = ns[i] / 4;
      total4 += ns[i] / 4;
    }
    cvt_f2bf<<<(total4 + 255) / 256, 256>>>(p, total4);
  }
  rope_tab<<<CT * 32 / 256, 256>>>(s->ropeC, s->ropeS);

  // 1. x = rmsnorm(hidden, ln1)
  rmsnorm_bf<<<CT, 256>>>(hidden, ln1, s->x);

  // 2. fused QKV low-rank projection (fp32 out)
  gemm_bf<0><<<dim3(12, 16, 1), 256, GSMEM>>>(
      s->x, s->qV, nullptr, s->Pqkv, nullptr, nullptr, nullptr, nullptr,
      nullptr, 1536, CD, 0);

  // 3. Us up-projections + RoPE
  proj_us_rope<<<dim3(CT / 32, CH), dim3(32, 8)>>>(
      s->Pqkv, q_Us, s->ropeC, s->ropeS, s->q, 1536, 1);
  proj_us_rope<<<dim3(CT / 32, CHK), dim3(32, 8)>>>(
      s->Pqkv + 1024, k_Us, s->ropeC, s->ropeS, s->k, 1536, 1);
  proj_us_rope<<<dim3(CT / 32, CHK), dim3(32, 8)>>>(
      s->Pqkv + 1280, v_Us, s->ropeC, s->ropeS, s->v, 1536, 0);

  // 4. attention
  flash_attn_bf<<<dim3(CT / 128, CH), 256, FA_SMEM_B>>>(s->q, s->k, s->v,
                                                        s->attn);

  // 5. output projection (split-K=2) + residual -> h
  gemm_bf<0><<<dim3(4, 16, 2), 256, GSMEM>>>(
      s->attn, s->oV, nullptr, s->skpart, nullptr, nullptr, nullptr, nullptr,
      nullptr, 512, CD, 1024);
  reduce_sk<<<CT * 512 / 1024, 256>>>(s->skpart, s->Po, CT * 512, 2);
  gemm_bf<0><<<dim3(16, 16, 1), 256, GSMEM>>>(
      s->Po, s->oUs, hidden, s->h, nullptr, nullptr, nullptr, nullptr,
      nullptr, CD, 512, 0);

  // 6. FFN
  rmsnorm_bf<<<CT, 256>>>(s->h, ln2, s->x);
  gemm_bf<1><<<dim3(4, 16, 2), 256, GSMEM>>>(
      s->x, s->gV, nullptr, s->Pg, s->x, s->uV, nullptr, s->Pu,
      nullptr, 512, CD, 0);
  gemm_bf<2><<<dim3(64, 16, 1), 256, GSMEM>>>(
      s->Pg, s->gUs, nullptr, s->gate, nullptr, nullptr, nullptr, nullptr,
      nullptr, CINTER, 512, 0);
  gemm_bf<3><<<dim3(64, 16, 1), 256, GSMEM>>>(
      s->Pu, s->uUs, nullptr, s->up, nullptr, nullptr, nullptr, nullptr,
      s->gate, CINTER, 512, 0);
  gemm_bf<0><<<dim3(4, 16, 4), 256, GSMEM>>>(
      s->up, s->dV, nullptr, s->skpart, nullptr, nullptr, nullptr, nullptr,
      nullptr, 512, CINTER, 2048);
  reduce_sk<<<CT * 512 / 1024, 256>>>(s->skpart, s->Pd, CT * 512, 4);
  gemm_bf<0><<<dim3(16, 16, 1), 256, GSMEM>>>(
      s->Pd, s->dUs, s->h, out, nullptr, nullptr, nullptr, nullptr,
      nullptr, CD, 512, 0);
}

// round 13
// speedup vs baseline: 1.2681x; 1.1226x over previous
#include <cuda_runtime.h>
#include <cuda_bf16.h>
#include <math.h>
#include <cstdint>

#define CT 2048
#define CD 2048
#define CH 32
#define CHK 8
#define CDH 64
#define CINTER 8192

typedef __nv_bfloat16 bf16;
typedef __nv_bfloat162 bf162;

// ---------------------------------------------------------------------------
// Static device scratch
// ---------------------------------------------------------------------------
struct alignas(256) Scratch {
  float Pqkv[CT * 1536];
  float h[CT * CD];
  float skpart[4 * CT * 512];
  float ropeC[CT * 32];
  float ropeS[CT * 32];
  bf16 x[CT * CD];
  bf16 q[CH * CT * CDH];
  bf16 k[CHK * CT * CDH];
  bf16 v[CHK * CT * CDH];
  bf16 attn[CT * CD];
  bf16 Po[CT * 512];
  bf16 Pg[CT * 512];
  bf16 Pu[CT * 512];
  bf16 gate[CT * CINTER];
  bf16 up[CT * CINTER];
  bf16 Pd[CT * 512];
  bf16 qV[1024 * CD];
  bf16 kV[256 * CD];
  bf16 vV[256 * CD];
  bf16 oUs[CD * 512];
  bf16 oV[512 * CD];
  bf16 gUs[CINTER * 512];
  bf16 gV[512 * CD];
  bf16 uUs[CINTER * 512];
  bf16 uV[512 * CD];
  bf16 dUs[CD * 512];
  bf16 dV[512 * CINTER];
};
__device__ Scratch g_scratch;

// ---------------------------------------------------------------------------
// helpers
// ---------------------------------------------------------------------------
__device__ __forceinline__ void cp16(void* s, const void* g) {
  uint32_t sa = (uint32_t)__cvta_generic_to_shared(s);
  asm volatile("cp.async.cg.shared.global [%0], [%1], 16;" ::"r"(sa), "l"(g));
}
__device__ __forceinline__ void mma_bf16(float* c, const uint32_t* a,
                                         const uint32_t* b) {
  asm volatile(
      "mma.sync.aligned.m16n8k16.row.col.f32.bf16.bf16.f32 "
      "{%0,%1,%2,%3}, {%4,%5,%6,%7}, {%8,%9}, {%0,%1,%2,%3};"
      : "+f"(c[0]), "+f"(c[1]), "+f"(c[2]), "+f"(c[3])
      : "r"(a[0]), "r"(a[1]), "r"(a[2]), "r"(a[3]), "r"(b[0]), "r"(b[1]));
}
__device__ __forceinline__ void ldm4(uint32_t* r, const void* p) {
  uint32_t a = (uint32_t)__cvta_generic_to_shared(p);
  asm volatile(
      "ldmatrix.sync.aligned.m8n8.x4.shared.b16 {%0,%1,%2,%3}, [%4];"
      : "=r"(r[0]), "=r"(r[1]), "=r"(r[2]), "=r"(r[3])
      : "r"(a));
}
__device__ __forceinline__ void ldm4t(uint32_t* r, const void* p) {
  uint32_t a = (uint32_t)__cvta_generic_to_shared(p);
  asm volatile(
      "ldmatrix.sync.aligned.m8n8.x4.trans.shared.b16 {%0,%1,%2,%3}, [%4];"
      : "=r"(r[0]), "=r"(r[1]), "=r"(r[2]), "=r"(r[3])
      : "r"(a));
}
__device__ __forceinline__ uint32_t packbf(float a, float b) {
  bf162 v = __floats2bfloat162_rn(a, b);
  return *(uint32_t*)&v;
}

// ---------------------------------------------------------------------------
// weight conversion fp32 -> bf16
// ---------------------------------------------------------------------------
#define NCVT 11
struct CvtPack {
  const float* src[NCVT];
  bf16* dst[NCVT];
  int n4[NCVT];
};
__global__ void cvt_f2bf(CvtPack p, int total4) {
  int i = blockIdx.x * 256 + threadIdx.x;
  if (i >= total4) return;
  int s = 0, off = i;
  while (off >= p.n4[s]) { off -= p.n4[s]; s++; }
  const float4 v = ((const float4*)p.src[s])[off];
  bf162* d = (bf162*)p.dst[s];
  d[off * 2] = __floats2bfloat162_rn(v.x, v.y);
  d[off * 2 + 1] = __floats2bfloat162_rn(v.z, v.w);
}

__global__ void rope_tab(float* __restrict__ c, float* __restrict__ s) {
  const int i = blockIdx.x * 256 + threadIdx.x;
  const int t = i >> 5, d = i & 31;
  const float invf = exp2f(-0.41524101186092028f * (float)d);
  float sn, cs;
  sincosf((float)t * invf, &sn, &cs);
  c[i] = cs;
  s[i] = sn;
}

// ---------------------------------------------------------------------------
// RMSNorm (fp32 in, bf16 out)
// ---------------------------------------------------------------------------
__global__ void rmsnorm_bf(const float* __restrict__ in,
                           const float* __restrict__ w,
                           bf16* __restrict__ out) {
  const int t = blockIdx.x;
  const float* row = in + (size_t)t * CD;
  float ss = 0.f;
  for (int i = threadIdx.x; i < CD; i += 256) {
    float v = row[i];
    ss += v * v;
  }
  __shared__ float red[8];
#pragma unroll
  for (int o = 16; o > 0; o >>= 1) ss += __shfl_xor_sync(0xffffffffu, ss, o);
  if ((threadIdx.x & 31) == 0) red[threadIdx.x >> 5] = ss;
  __syncthreads();
  if (threadIdx.x == 0) {
    float v = 0.f;
#pragma unroll
    for (int i = 0; i < 8; i++) v += red[i];
    red[0] = v;
  }
  __syncthreads();
  const float inv = rsqrtf(red[0] * (1.0f / CD) + 1e-5f);
  for (int i = threadIdx.x * 2; i < CD; i += 512) {
    bf162 o = __floats2bfloat162_rn(row[i] * inv * w[i],
                                    row[i + 1] * inv * w[i + 1]);
    *(bf162*)&out[(size_t)t * CD + i] = o;
  }
}

// ---------------------------------------------------------------------------
// bf16 GEMM (NT), KT=64 per stage, 3-stage cp.async ring. 128x128 CTA tile.
// MODE 0: fp32 out (+res). 1: bf16. 2: bf16 silu. 3: bf16 *aux.
// kc>0: split-K; else blockIdx.z picks problem pair.
// ---------------------------------------------------------------------------
#define GST 3
#define GSR 72                 // row stride (bf16) for K=64 tiles
#define GTILE (128 * GSR)      // elems per tile
#define GSMEM (2 * GST * GTILE * 2)

template <int MODE>
__global__ __launch_bounds__(256, 2) void gemm_bf(
    const bf16* __restrict__ A1, const bf16* __restrict__ B1,
    const float* __restrict__ res1, void* __restrict__ C1,
    const bf16* __restrict__ A2, const bf16* __restrict__ B2,
    const float* __restrict__ res2, void* __restrict__ C2,
    const bf16* __restrict__ aux, int N, int K, int kc) {
  extern __shared__ bf16 dynsm[];
  bf16* As = dynsm;
  bf16* Bs = dynsm + GST * GTILE;

  const bf16* A;
  const bf16* B;
  const float* res;
  void* C;
  int kbase, Kc;
  if (kc > 0) {
    A = A1; B = B1; res = nullptr;
    C = (char*)C1 + (size_t)blockIdx.z * CT * N * 4;
    kbase = blockIdx.z * kc;
    Kc = kc;
  } else {
    A = blockIdx.z ? A2 : A1;
    B = blockIdx.z ? B2 : B1;
    res = blockIdx.z ? res2 : res1;
    C = blockIdx.z ? C2 : C1;
    kbase = 0;
    Kc = K;
  }

  const int tid = threadIdx.x;
  const int lane = tid & 31, warp = tid >> 5;
  const int wm = (warp & 1) * 64, wn = (warp >> 1) * 32;
  const int bm = blockIdx.y * 128, bn = blockIdx.x * 128;
  const int gi = lane >> 2, ti = lane & 3;

  float acc[4][4][4];
#pragma unroll
  for (int i = 0; i < 4; i++)
#pragma unroll
    for (int j = 0; j < 4; j++)
#pragma unroll
      for (int l = 0; l < 4; l++) acc[i][j][l] = 0.f;

  const int nt = Kc >> 6;

  // loader mapping: 4 granules per tile per thread; g = tid + i*256
  // row = g>>3 (0..127), col8 = (g&7)*8
  int lrow[4], lcol[4];
#pragma unroll
  for (int i = 0; i < 4; i++) {
    const int g = tid + i * 256;
    lrow[i] = g >> 3;
    lcol[i] = (g & 7) * 8;
  }

  auto load_stage = [&](int st, int kt) {
    const int k0 = kbase + (kt << 6);
#pragma unroll
    for (int i = 0; i < 4; i++) {
      const int so = st * GTILE + lrow[i] * GSR + lcol[i];
      cp16(&As[so], &A[(size_t)(bm + lrow[i]) * K + k0 + lcol[i]]);
      cp16(&Bs[so], &B[(size_t)(bn + lrow[i]) * K + k0 + lcol[i]]);
    }
  };

#pragma unroll
  for (int s = 0; s < GST - 1; s++) {
    load_stage(s, s);
    asm volatile("cp.async.commit_group;" ::: "memory");
  }

  const int arow = wm + (lane & 15);
  const int acol = (lane >> 4) * 8;
  const int g8 = lane >> 3;
  const int brow = wn + (g8 >> 1) * 8 + (lane & 7);
  const int bcol = (g8 & 1) * 8;

  for (int t = 0; t < nt; t++) {
    asm volatile("cp.async.wait_group %0;" ::"n"(GST - 2) : "memory");
    __syncthreads();
    const int pf = t + GST - 1;
    if (pf < nt) load_stage(pf % GST, pf);
    asm volatile("cp.async.commit_group;" ::: "memory");

    const int buf = t % GST;
    bf16* Ab = As + buf * GTILE;
    bf16* Bb = Bs + buf * GTILE;
#pragma unroll
    for (int ks = 0; ks < 4; ks++) {
      uint32_t a[4][4], b[2][4];
#pragma unroll
      for (int fm = 0; fm < 4; fm++)
        ldm4(a[fm], &Ab[(arow + fm * 16) * GSR + ks * 16 + acol]);
      ldm4(b[0], &Bb[brow * GSR + ks * 16 + bcol]);
      ldm4(b[1], &Bb[(brow + 16) * GSR + ks * 16 + bcol]);
#pragma unroll
      for (int fm = 0; fm < 4; fm++)
#pragma unroll
        for (int fn = 0; fn < 4; fn++)
          mma_bf16(acc[fm][fn], a[fm], &b[fn >> 1][(fn & 1) * 2]);
    }
  }

#pragma unroll
  for (int fm = 0; fm < 4; fm++) {
#pragma unroll
    for (int fn = 0; fn < 4; fn++) {
      const int r = bm + wm + fm * 16 + gi;
      const int c = bn + wn + fn * 8 + ti * 2;
      float v[4] = {acc[fm][fn][0], acc[fm][fn][1], acc[fm][fn][2],
                    acc[fm][fn][3]};
      if (MODE == 0) {
        float* Cf = (float*)C;
        if (res) {
          const float2 r0 = *(const float2*)&res[(size_t)r * N + c];
          const float2 r1 = *(const float2*)&res[(size_t)(r + 8) * N + c];
          v[0] += r0.x; v[1] += r0.y; v[2] += r1.x; v[3] += r1.y;
        }
        *(float2*)&Cf[(size_t)r * N + c] = make_float2(v[0], v[1]);
        *(float2*)&Cf[(size_t)(r + 8) * N + c] = make_float2(v[2], v[3]);
      } else {
        if (MODE == 2) {
#pragma unroll
          for (int l = 0; l < 4; l++) v[l] = v[l] / (1.f + __expf(-v[l]));
        }
        if (MODE == 3) {
          const bf162 a0 = *(const bf162*)&aux[(size_t)r * N + c];
          const bf162 a1 = *(const bf162*)&aux[(size_t)(r + 8) * N + c];
          v[0] *= __bfloat162float(a0.x); v[1] *= __bfloat162float(a0.y);
          v[2] *= __bfloat162float(a1.x); v[3] *= __bfloat162float(a1.y);
        }
        bf16* Cb = (bf16*)C;
        *(bf162*)&Cb[(size_t)r * N + c] = __floats2bfloat162_rn(v[0], v[1]);
        *(bf162*)&Cb[(size_t)(r + 8) * N + c] =
            __floats2bfloat162_rn(v[2], v[3]);
      }
    }
  }
}

__global__ void reduce_sk(const float* __restrict__ part,
                          bf16* __restrict__ out, int MN, int S) {
  const int i = (blockIdx.x * 256 + threadIdx.x) * 4;
  if (i >= MN) return;
  float4 a = *(const float4*)&part[i];
  for (int s = 1; s < S; s++) {
    const float4 p = *(const float4*)&part[(size_t)s * MN + i];
    a.x += p.x; a.y += p.y; a.z += p.z; a.w += p.w;
  }
  *(bf162*)&out[i] = __floats2bfloat162_rn(a.x, a.y);
  *(bf162*)&out[i + 2] = __floats2bfloat162_rn(a.z, a.w);
}

// ---------------------------------------------------------------------------
// Merged per-head Us projection + RoPE for q/k/v in one launch.
// grid (CT/32, 48): slots 0..31 q(rope), 32..39 k(rope), 40..47 v(no rope).
// ---------------------------------------------------------------------------
__global__ void proj_us_rope_all(
    const float* __restrict__ P, const float* __restrict__ qUs,
    const float* __restrict__ kUs, const float* __restrict__ vUs,
    const float* __restrict__ tC, const float* __restrict__ tS,
    bf16* __restrict__ qo, bf16* __restrict__ ko, bf16* __restrict__ vo) {
  const int slot = blockIdx.y;
  const float* Us;
  int poff, doRope;
  bf16* out;
  if (slot < 32) {
    Us = qUs + (size_t)slot * 2048;
    poff = slot * 32;
    out = qo + (size_t)slot * CT * CDH;
    doRope = 1;
  } else if (slot < 40) {
    const int hh = slot - 32;
    Us = kUs + (size_t)hh * 2048;
    poff = 1024 + hh * 32;
    out = ko + (size_t)hh * CT * CDH;
    doRope = 1;
  } else {
    const int hh = slot - 40;
    Us = vUs + (size_t)hh * 2048;
    poff = 1280 + hh * 32;
    out = vo + (size_t)hh * CT * CDH;
    doRope = 0;
  }

  const int tg = threadIdx.y;
  const int dh = threadIdx.x;
  const int t0 = blockIdx.x * 32 + tg * 4;
  __shared__ float sUs[64][33];
  __shared__ float sP[32][33];
  const int tid = tg * 32 + dh;
#pragma unroll
  for (int i = tid; i < 64 * 32; i += 256) sUs[i >> 5][i & 31] = Us[i];
#pragma unroll
  for (int j = 0; j < 4; j++)
    sP[tg * 4 + j][dh] = P[(size_t)(t0 + j) * 1536 + poff + dh];
  __syncthreads();
  float x1[4] = {0.f, 0.f, 0.f, 0.f}, x2[4] = {0.f, 0.f, 0.f, 0.f};
#pragma unroll
  for (int r = 0; r < 32; r++) {
    const float u1 = sUs[dh][r];
    const float u2 = sUs[dh + 32][r];
#pragma unroll
    for (int j = 0; j < 4; j++) {
      const float p = sP[tg * 4 + j][r];
      x1[j] = fmaf(p, u1, x1[j]);
      x2[j] = fmaf(p, u2, x2[j]);
    }
  }
#pragma unroll
  for (int j = 0; j < 4; j++) {
    float o1 = x1[j], o2 = x2[j];
    if (doRope) {
      const float cs = tC[(t0 + j) * 32 + dh];
      const float sn = tS[(t0 + j) * 32 + dh];
      o1 = x1[j] * cs - x2[j] * sn;
      o2 = x2[j] * cs + x1[j] * sn;
    }
    const size_t base = (size_t)(t0 + j) * CDH;
    out[base + dh] = __float2bfloat16(o1);
    out[base + dh + 32] = __float2bfloat16(o2);
  }
}

// ---------------------------------------------------------------------------
// bf16 causal flash attention, FA2-style. Q tile 128 rows, 8 warps x 16 rows.
// V fed via ldmatrix.trans; K/V cp.async double-buffered. (R12 config)
// ---------------------------------------------------------------------------
#define FTS2 72
#define FA_Q_FLOATS (128 * FTS2)
#define FA_KV_FLOATS (64 * FTS2)
#define FA_SMEM_B ((FA_Q_FLOATS + 4 * FA_KV_FLOATS) * 2)
__global__ __launch_bounds__(256) void flash_attn_bf(
    const bf16* __restrict__ Q, const bf16* __restrict__ Kg,
    const bf16* __restrict__ Vg, bf16* __restrict__ Og) {
  extern __shared__ bf16 fasm[];
  bf16* Qs = fasm;
  bf16* Ks = fasm + FA_Q_FLOATS;
  bf16* Vs = Ks + 2 * FA_KV_FLOATS;

  const int qb = blockIdx.x, hh = blockIdx.y, hk = hh >> 2;
  const int tid = threadIdx.x;
  const int lane = tid & 31, warp = tid >> 5;
  const int gi = lane >> 2, ti = lane & 3;
  const int wm = warp * 16;
  const int ldr = tid >> 3, c8 = (tid & 7) * 8;

#pragma unroll
  for (int r = 0; r < 4; r++) {
    const int row = ldr + r * 32;
    cp16(&Qs[row * FTS2 + c8],
         &Q[((size_t)hh * CT + qb * 128 + row) * 64 + c8]);
  }
  asm volatile("cp.async.commit_group;" ::: "memory");

  auto load_kv = [&](int buf, int kb) {
    bf16* kd = Ks + buf * FA_KV_FLOATS;
    bf16* vd = Vs + buf * FA_KV_FLOATS;
#pragma unroll
    for (int r = 0; r < 2; r++) {
      const int row = ldr + r * 32;
      const size_t gbase = ((size_t)hk * CT + kb * 64 + row) * 64 + c8;
      cp16(&kd[row * FTS2 + c8], &Kg[gbase]);
      cp16(&vd[row * FTS2 + c8], &Vg[gbase]);
    }
  };

  load_kv(0, 0);
  asm volatile("cp.async.commit_group;" ::: "memory");
  asm volatile("cp.async.wait_group 0;" ::: "memory");
  __syncthreads();

  const int arow_ = wm + (lane & 15);
  const int acol = (lane >> 4) * 8;
  uint32_t aq[4][4];
#pragma unroll
  for (int ks = 0; ks < 4; ks++)
    ldm4(aq[ks], &Qs[arow_ * FTS2 + ks * 16 + acol]);

  const int g8 = lane >> 3;
  const int nbrow = (g8 >> 1) * 8 + (lane & 7);
  const int bcol = (g8 & 1) * 8;
  const int tkrow = (g8 & 1) * 8 + (lane & 7);
  const int tncol = (g8 >> 1) * 8;

  float m0 = -1e30f, m1 = -1e30f, l0 = 0.f, l1 = 0.f;
  float oacc[8][4];
#pragma unroll
  for (int i = 0; i < 8; i++)
#pragma unroll
    for (int j = 0; j < 4; j++) oacc[i][j] = 0.f;

  const int row0 = qb * 128 + wm + gi;
  const int kbmax = 2 * qb + 1;

  for (int kb = 0; kb <= kbmax; kb++) {
    const int buf = kb & 1;
    if (kb > 0) {
      asm volatile("cp.async.wait_group 0;" ::: "memory");
    }
    __syncthreads();
    if (kb < kbmax) {
      load_kv(buf ^ 1, kb + 1);
      asm volatile("cp.async.commit_group;" ::: "memory");
    }
    bf16* Kb = Ks + buf * FA_KV_FLOATS;
    bf16* Vb = Vs + buf * FA_KV_FLOATS;

    float sacc[8][4];
#pragma unroll
    for (int i = 0; i < 8; i++)
#pragma unroll
      for (int j = 0; j < 4; j++) sacc[i][j] = 0.f;
#pragma unroll
    for (int ks = 0; ks < 4; ks++) {
      uint32_t b[4][4];
#pragma unroll
      for (int nb = 0; nb < 4; nb++)
        ldm4(b[nb], &Kb[(nbrow + nb * 16) * FTS2 + ks * 16 + bcol]);
#pragma unroll
      for (int fn = 0; fn < 8; fn++)
        mma_bf16(sacc[fn], aq[ks], &b[fn >> 1][(fn & 1) * 2]);
    }

    const bool needMask = (kb * 64 + 63) > row0;
    float rmax0 = -1e30f, rmax1 = -1e30f;
#pragma unroll
    for (int fn = 0; fn < 8; fn++) {
      const int c = kb * 64 + fn * 8 + 2 * ti;
#pragma unroll
      for (int l = 0; l < 4; l++) {
        float v = sacc[fn][l] * 0.125f;
        if (needMask) {
          const int row = row0 + ((l >= 2) ? 8 : 0);
          if (c + (l & 1) > row) v = -1e30f;
        }
        sacc[fn][l] = v;
        if (l >= 2) rmax1 = fmaxf(rmax1, v);
        else rmax0 = fmaxf(rmax0, v);
      }
    }
    rmax0 = fmaxf(rmax0, __shfl_xor_sync(0xffffffffu, rmax0, 1));
    rmax0 = fmaxf(rmax0, __shfl_xor_sync(0xffffffffu, rmax0, 2));
    rmax1 = fmaxf(rmax1, __shfl_xor_sync(0xffffffffu, rmax1, 1));
    rmax1 = fmaxf(rmax1, __shfl_xor_sync(0xffffffffu, rmax1, 2));
    const float mn0 = fmaxf(m0, rmax0), mn1 = fmaxf(m1, rmax1);
    const float al0 = __expf(m0 - mn0), al1 = __expf(m1 - mn1);
    m0 = mn0; m1 = mn1;

    float rs0 = 0.f, rs1 = 0.f;
    uint32_t ap[4][4];
#pragma unroll
    for (int ks = 0; ks < 4; ks++) {
      const int f0 = 2 * ks, f1 = 2 * ks + 1;
      const float p00 = __expf(sacc[f0][0] - m0);
      const float p01 = __expf(sacc[f0][1] - m0);
      const float p02 = __expf(sacc[f0][2] - m1);
      const float p03 = __expf(sacc[f0][3] - m1);
      const float p10 = __expf(sacc[f1][0] - m0);
      const float p11 = __expf(sacc[f1][1] - m0);
      const float p12 = __expf(sacc[f1][2] - m1);
      const float p13 = __expf(sacc[f1][3] - m1);
      rs0 += p00 + p01 + p10 + p11;
      rs1 += p02 + p03 + p12 + p13;
      ap[ks][0] = packbf(p00, p01);
      ap[ks][1] = packbf(p02, p03);
      ap[ks][2] = packbf(p10, p11);
      ap[ks][3] = packbf(p12, p13);
    }
    rs0 += __shfl_xor_sync(0xffffffffu, rs0, 1);
    rs0 += __shfl_xor_sync(0xffffffffu, rs0, 2);
    rs1 += __shfl_xor_sync(0xffffffffu, rs1, 1);
    rs1 += __shfl_xor_sync(0xffffffffu, rs1, 2);
    l0 = l0 * al0 + rs0;
    l1 = l1 * al1 + rs1;
#pragma unroll
    for (int fn = 0; fn < 8; fn++) {
      oacc[fn][0] *= al0; oacc[fn][1] *= al0;
      oacc[fn][2] *= al1; oacc[fn][3] *= al1;
    }

#pragma unroll
    for (int ks = 0; ks < 4; ks++) {
      uint32_t b[4][4];
#pragma unroll
      for (int nb = 0; nb < 4; nb++)
        ldm4t(b[nb], &Vb[(ks * 16 + tkrow) * FTS2 + nb * 16 + tncol]);
#pragma unroll
      for (int fn = 0; fn < 8; fn++)
        mma_bf16(oacc[fn], ap[ks], &b[fn >> 1][(fn & 1) * 2]);
    }
  }

  const float inv0 = 1.f / l0, inv1 = 1.f / l1;
#pragma unroll
  for (int fn = 0; fn < 8; fn++) {
    const int col = hh * 64 + fn * 8 + 2 * ti;
    *(bf162*)&Og[(size_t)(row0) * CD + col] =
        __floats2bfloat162_rn(oacc[fn][0] * inv0, oacc[fn][1] * inv0);
    *(bf162*)&Og[(size_t)(row0 + 8) * CD + col] =
        __floats2bfloat162_rn(oacc[fn][2] * inv1, oacc[fn][3] * inv1);
  }
}

// ---------------------------------------------------------------------------
// Launch pipeline
// ---------------------------------------------------------------------------
extern "C" void kernel_launch(void* const* d_in, const int* in_sizes, int n_in,
                              void* d_out, int out_size) {
  const float* hidden = (const float*)d_in[0];
  const float* ln1 = (const float*)d_in[1];
  const float* ln2 = (const float*)d_in[2];
  const float* q_Us = (const float*)d_in[3];
  const float* q_V  = (const float*)d_in[4];
  const float* k_Us = (const float*)d_in[5];
  const float* k_V  = (const float*)d_in[6];
  const float* v_Us = (const float*)d_in[7];
  const float* v_V  = (const float*)d_in[8];
  const float* o_Us = (const float*)d_in[9];
  const float* o_V  = (const float*)d_in[10];
  const float* g_Us = (const float*)d_in[11];
  const float* g_V  = (const float*)d_in[12];
  const float* u_Us = (const float*)d_in[13];
  const float* u_V  = (const float*)d_in[14];
  const float* d_Us = (const float*)d_in[15];
  const float* d_V  = (const float*)d_in[16];
  float* out = (float*)d_out;

  Scratch* s = nullptr;
  cudaGetSymbolAddress((void**)&s, g_scratch);

  cudaFuncSetAttribute(gemm_bf<0>,
                       cudaFuncAttributeMaxDynamicSharedMemorySize, GSMEM);
  cudaFuncSetAttribute(gemm_bf<1>,
                       cudaFuncAttributeMaxDynamicSharedMemorySize, GSMEM);
  cudaFuncSetAttribute(gemm_bf<2>,
                       cudaFuncAttributeMaxDynamicSharedMemorySize, GSMEM);
  cudaFuncSetAttribute(gemm_bf<3>,
                       cudaFuncAttributeMaxDynamicSharedMemorySize, GSMEM);
  cudaFuncSetAttribute(flash_attn_bf,
                       cudaFuncAttributeMaxDynamicSharedMemorySize, FA_SMEM_B);

  // 0. weight conversion + rope table
  {
    CvtPack p;
    const float* srcs[NCVT] = {q_V, k_V, v_V, o_Us, o_V, g_Us,
                               g_V, u_Us, u_V, d_Us, d_V};
    bf16* dsts[NCVT] = {s->qV, s->kV, s->vV, s->oUs, s->oV, s->gUs,
                        s->gV, s->uUs, s->uV, s->dUs, s->dV};
    const int ns[NCVT] = {1024 * CD, 256 * CD, 256 * CD, CD * 512, 512 * CD,
                          CINTER * 512, 512 * CD, CINTER * 512, 512 * CD,
                          CD * 512, 512 * CINTER};
    int total4 = 0;
    for (int i = 0; i < NCVT; i++) {
      p.src[i] = srcs[i]; p.dst[i] = dsts[i]; p.n4[i] = ns[i] / 4;
      total4 += ns[i] / 4;
    }
    cvt_f2bf<<<(total4 + 255) / 256, 256>>>(p, total4);
  }
  rope_tab<<<CT * 32 / 256, 256>>>(s->ropeC, s->ropeS);

  // 1. x = rmsnorm(hidden, ln1)
  rmsnorm_bf<<<CT, 256>>>(hidden, ln1, s->x);

  // 2. fused QKV low-rank projection (fp32 out)
  gemm_bf<0><<<dim3(12, 16, 1), 256, GSMEM>>>(
      s->x, s->qV, nullptr, s->Pqkv, nullptr, nullptr, nullptr, nullptr,
      nullptr, 1536, CD, 0);

  // 3. merged Us up-projections + RoPE (q|k|v in one launch)
  proj_us_rope_all<<<dim3(CT / 32, 48), dim3(32, 8)>>>(
      s->Pqkv, q_Us, k_Us, v_Us, s->ropeC, s->ropeS, s->q, s->k, s->v);

  // 4. attention
  flash_attn_bf<<<dim3(CT / 128, CH), 256, FA_SMEM_B>>>(s->q, s->k, s->v,
                                                        s->attn);

  // 5. output projection (split-K=2) + residual -> h
  gemm_bf<0><<<dim3(4, 16, 2), 256, GSMEM>>>(
      s->attn, s->oV, nullptr, s->skpart, nullptr, nullptr, nullptr, nullptr,
      nullptr, 512, CD, 1024);
  reduce_sk<<<CT * 512 / 1024, 256>>>(s->skpart, s->Po, CT * 512, 2);
  gemm_bf<0><<<dim3(16, 16, 1), 256, GSMEM>>>(
      s->Po, s->oUs, hidden, s->h, nullptr, nullptr, nullptr, nullptr,
      nullptr, CD, 512, 0);

  // 6. FFN
  rmsnorm_bf<<<CT, 256>>>(s->h, ln2, s->x);
  gemm_bf<1><<<dim3(4, 16, 2), 256, GSMEM>>>(
      s->x, s->gV, nullptr, s->Pg, s->x, s->uV, nullptr, s->Pu,
      nullptr, 512, CD, 0);
  gemm_bf<2><<<dim3(64, 16, 1), 256, GSMEM>>>(
      s->Pg, s->gUs, nullptr, s->gate, nullptr, nullptr, nullptr, nullptr,
      nullptr, CINTER, 512, 0);
  gemm_bf<3><<<dim3(64, 16, 1), 256, GSMEM>>>(
      s->Pu, s->uUs, nullptr, s->up, nullptr, nullptr, nullptr, nullptr,
      s->gate, CINTER, 512, 0);
  gemm_bf<0><<<dim3(4, 16, 4), 256, GSMEM>>>(
      s->up, s->dV, nullptr, s->skpart, nullptr, nullptr, nullptr, nullptr,
      nullptr, 512, CINTER, 2048);
  reduce_sk<<<CT * 512 / 1024, 256>>>(s->skpart, s->Pd, CT * 512, 4);
  gemm_bf<0><<<dim3(16, 16, 1), 256, GSMEM>>>(
      s->Pd, s->dUs, s->h, out, nullptr, nullptr, nullptr, nullptr,
      nullptr, CD, 512, 0);
}